// round 16
// baseline (speedup 1.0000x reference)
#include <cuda_runtime.h>
#include <cuda_bf16.h>
#include <cstdint>

#define NN   50000
#define EE   1000000
#define BB   2048
#define RR   3
#define INP  256
#define HID  512
#define OUTC 256
#define BN_EPS 1e-5f
#define K2_1 (2*INP)    // 512  (hi|lo storage for GEMM1 operands)
#define K2_2 (2*HID)    // 1024 (hi|lo storage for GEMM2 operands)

// ---------------- device scratch ----------------
__device__ int   g_pos[NN];
__device__ int   g_appear[RR][BB];
__device__ float g_deg[RR][BB];
__device__ int   g_kept[RR];
__device__ int   g_ks[RR][EE];
__device__ int   g_kd[RR][EE];
__device__ __align__(16) __nv_bfloat16 g_A1[RR * BB * K2_1];
__device__ __align__(16) __nv_bfloat16 g_B1[HID * K2_1];
__device__ __align__(16) __nv_bfloat16 g_A2[RR * BB * K2_2];
__device__ __align__(16) __nv_bfloat16 g_B2[OUTC * K2_2];
__device__ __align__(16) float g_XW[RR * BB * HID];
__device__ __align__(16) float g_AGG[RR * BB * HID];
__device__ __align__(16) float g_HW[RR * BB * OUTC];
__device__ float g_sum[RR][HID];
__device__ float g_sumsq[RR][HID];

// ---------------- helpers ----------------
__device__ __forceinline__ uint32_t smem_u32(const void* p) {
    uint32_t a;
    asm("{ .reg .u64 t; cvta.to.shared.u64 t, %1; cvt.u32.u64 %0, t; }"
        : "=r"(a) : "l"(p));
    return a;
}
__device__ __forceinline__ void ldsm_x4(uint32_t& r0, uint32_t& r1,
                                        uint32_t& r2, uint32_t& r3, uint32_t a) {
    asm volatile("ldmatrix.sync.aligned.m8n8.x4.shared.b16 {%0,%1,%2,%3}, [%4];"
                 : "=r"(r0), "=r"(r1), "=r"(r2), "=r"(r3) : "r"(a));
}
__device__ __forceinline__ void mma16816(float* d, const uint32_t* a,
                                         const uint32_t* b) {
    asm volatile(
        "mma.sync.aligned.m16n8k16.row.col.f32.bf16.bf16.f32 "
        "{%0,%1,%2,%3}, {%4,%5,%6,%7}, {%8,%9}, {%0,%1,%2,%3};"
        : "+f"(d[0]), "+f"(d[1]), "+f"(d[2]), "+f"(d[3])
        : "r"(a[0]), "r"(a[1]), "r"(a[2]), "r"(a[3]), "r"(b[0]), "r"(b[1]));
}
__device__ __forceinline__ void split2(float x, __nv_bfloat16& hi, __nv_bfloat16& lo) {
    hi = __float2bfloat16(x);
    lo = __float2bfloat16(x - __bfloat162float(hi));
}

// ---------------- fused prologue ----------------
__global__ void k_pre(const float* __restrict__ W1, const float* __restrict__ W2,
                      const float* __restrict__ feat, const int* __restrict__ bn) {
    int idx = blockIdx.x * blockDim.x + threadIdx.x;   // grid: RR*BB*INP threads
    if (idx < RR * BB * INP) {
        int c = idx & (INP - 1);
        int i = (idx >> 8) & (BB - 1);
        int r = idx >> 19;
        float x = feat[((size_t)r * NN + bn[i]) * INP + c];
        __nv_bfloat16 hi, lo; split2(x, hi, lo);
        size_t base = ((size_t)r * BB + i) * K2_1;
        g_A1[base + c] = hi;
        g_A1[base + INP + c] = lo;
    }
    if (idx < RR * BB * HID / 4)
        ((float4*)g_AGG)[idx] = make_float4(0.f, 0.f, 0.f, 0.f);
    if (idx < NN) {
        int lo = 0, hi = BB - 1, res = -1;
        while (lo <= hi) {
            int mid = (lo + hi) >> 1;
            int v = bn[mid];
            if (v == idx) { res = mid; break; }
            if (v < idx) lo = mid + 1; else hi = mid - 1;
        }
        g_pos[idx] = res;
    }
    if (idx < RR * BB) ((int*)g_appear)[idx] = 0;
    if (idx < RR * HID) { ((float*)g_sum)[idx] = 0.f; ((float*)g_sumsq)[idx] = 0.f; }
    if (idx < RR) g_kept[idx] = 0;
    if (idx < HID * INP) {
        int n = idx >> 8, k = idx & (INP - 1);
        __nv_bfloat16 hi2, lo2; split2(W1[(size_t)k * HID + n], hi2, lo2);
        size_t base = (size_t)n * K2_1;
        g_B1[base + k] = hi2;
        g_B1[base + INP + k] = lo2;
    }
    if (idx < OUTC * HID) {
        int n = idx >> 9, k = idx & (HID - 1);
        __nv_bfloat16 hi2, lo2; split2(W2[(size_t)k * OUTC + n], hi2, lo2);
        size_t base = (size_t)n * K2_2;
        g_B2[base + k] = hi2;
        g_B2[base + HID + k] = lo2;
    }
}

// ---------------- edge filtering (batched) ----------------
__global__ void k_scan(const int4* __restrict__ ei4) {
    const int r = blockIdx.y;
    const int4* src4 = ei4 + (size_t)r * 2 * (EE / 4);
    const int4* dst4 = src4 + EE / 4;
    int i = blockIdx.x * blockDim.x + threadIdx.x;
    if (i >= EE / 4) return;
    int4 s = src4[i], d = dst4[i];
    int ss[4] = {s.x, s.y, s.z, s.w};
    int dd[4] = {d.x, d.y, d.z, d.w};
#pragma unroll
    for (int j = 0; j < 4; j++) {
        int ps = g_pos[ss[j]];
        int pd = g_pos[dd[j]];
        if ((ps | pd) >= 0) {
            g_appear[r][ps] = 1;
            g_appear[r][pd] = 1;
            int ix = atomicAdd(&g_kept[r], 1);
            g_ks[r][ix] = ps;
            g_kd[r][ix] = pd;
        }
    }
}

// prefix scan + renumber + degree, one block per relation (1024 threads)
__global__ void __launch_bounds__(1024)
k_prefix_renum() {
    const int r = blockIdx.x;
    const int t = threadIdx.x;
    __shared__ int sc[1024];
    __shared__ int srank[BB];
    __shared__ float sdeg[BB];
    int a0 = g_appear[r][2 * t], a1 = g_appear[r][2 * t + 1];
    sc[t] = a0 + a1;
    sdeg[2 * t] = 0.f;
    sdeg[2 * t + 1] = 0.f;
    __syncthreads();
    for (int off = 1; off < 1024; off <<= 1) {
        int x = (t >= off) ? sc[t - off] : 0;
        __syncthreads();
        sc[t] += x;
        __syncthreads();
    }
    int pre = (t > 0) ? sc[t - 1] : 0;
    srank[2 * t] = pre + a0 - 1;
    srank[2 * t + 1] = pre + a0 + a1 - 1;
    __syncthreads();
    int ne = g_kept[r];
    for (int e = t; e < ne; e += 1024) {
        int rs = srank[g_ks[r][e]];
        int rd = srank[g_kd[r][e]];
        g_ks[r][e] = rs;
        g_kd[r][e] = rd;
        atomicAdd(&sdeg[rd], 1.0f);
    }
    __syncthreads();
    g_deg[r][2 * t] = 1.0f + sdeg[2 * t];
    g_deg[r][2 * t + 1] = 1.0f + sdeg[2 * t + 1];
}

// ---------------- HMMA GEMM (R12 core; chunk->segment mapping) ------------
// Operands stored [hi|lo] (2*SEGK row stride). Virtual K = 3*SEGK with
// segment pairs (Ahi,Bhi), (Alo,Bhi), (Ahi,Blo).
// EPI=0: write XW only.  EPI=1: write HW and out = HW/deg + b2.
template <int SEGK, int NTOT, int NTILE, int EPI>
__device__ __forceinline__ void hmma_body(const __nv_bfloat16* __restrict__ Aall,
                                          const __nv_bfloat16* __restrict__ BT,
                                          float* __restrict__ outall,
                                          const float* __restrict__ b2) {
    constexpr int K2 = 2 * SEGK;
    constexpr int GRP = SEGK / 64;            // chunks per segment group
    constexpr int NCH = 3 * GRP;
    constexpr int NW = NTILE / 2;
    constexpr int NF = NW / 8;
    __shared__ alignas(1024) __nv_bfloat16 sA[128 * 64];
    __shared__ alignas(1024) __nv_bfloat16 sB[NTILE * 64];

    const int tid = threadIdx.x, wid = tid >> 5, lid = tid & 31;
    const int mwarp = wid & 3, nwarp = wid >> 2;
    const int rel = blockIdx.z;
    const int m0 = blockIdx.y * 128, n0 = blockIdx.x * NTILE;
    const __nv_bfloat16* A = Aall + (size_t)rel * BB * K2;
    const uint32_t sA0 = smem_u32(sA), sB0 = smem_u32(sB);

    float acc[2][NF][4];
#pragma unroll
    for (int mi = 0; mi < 2; mi++)
#pragma unroll
        for (int nf = 0; nf < NF; nf++)
#pragma unroll
            for (int j = 0; j < 4; j++) acc[mi][nf][j] = 0.0f;

    const int a_row = lid & 15, a_kb = (lid >> 4) * 16;
    const int b_nn = ((lid >> 4) << 3) + (lid & 7), b_kb = ((lid >> 3) & 1) * 16;

    for (int ch = 0; ch < NCH; ch++) {
        const int g = ch / GRP;
        const int inner = (ch - g * GRP) * 64;
        const int aoff = (g == 1 ? SEGK : 0) + inner;   // A: hi,lo,hi
        const int boff = (g == 2 ? SEGK : 0) + inner;   // B: hi,hi,lo
#pragma unroll
        for (int it = 0; it < 4; it++) {
            int idx = it * 256 + tid;
            int r = idx >> 3, c16 = idx & 7;
            uint32_t byte = (uint32_t)(r * 128 + c16 * 16);
            uint32_t sw = byte ^ ((byte >> 3) & 0x70);
            *(uint4*)((char*)sA + sw) =
                *(const uint4*)(A + (size_t)(m0 + r) * K2 + aoff + c16 * 8);
        }
#pragma unroll
        for (int it = 0; it < NTILE / 32; it++) {
            int idx = it * 256 + tid;
            int r = idx >> 3, c16 = idx & 7;
            uint32_t byte = (uint32_t)(r * 128 + c16 * 16);
            uint32_t sw = byte ^ ((byte >> 3) & 0x70);
            *(uint4*)((char*)sB + sw) =
                *(const uint4*)(BT + (size_t)(n0 + r) * K2 + boff + c16 * 8);
        }
        __syncthreads();
#pragma unroll
        for (int ks = 0; ks < 4; ks++) {
            const int kbyte = ks * 32;
            uint32_t af[2][4];
#pragma unroll
            for (int mi = 0; mi < 2; mi++) {
                int row = mwarp * 32 + mi * 16 + a_row;
                uint32_t byte = (uint32_t)(row * 128 + kbyte + a_kb);
                uint32_t sw = byte ^ ((byte >> 3) & 0x70);
                ldsm_x4(af[mi][0], af[mi][1], af[mi][2], af[mi][3], sA0 + sw);
            }
            uint32_t bf_[NF][2];
#pragma unroll
            for (int np = 0; np < NF / 2; np++) {
                int nn = nwarp * NW + np * 16 + b_nn;
                uint32_t byte = (uint32_t)(nn * 128 + kbyte + b_kb);
                uint32_t sw = byte ^ ((byte >> 3) & 0x70);
                uint32_t r0, r1, r2, r3;
                ldsm_x4(r0, r1, r2, r3, sB0 + sw);
                bf_[2 * np][0] = r0; bf_[2 * np][1] = r1;
                bf_[2 * np + 1][0] = r2; bf_[2 * np + 1][1] = r3;
            }
#pragma unroll
            for (int mi = 0; mi < 2; mi++)
#pragma unroll
                for (int nf = 0; nf < NF; nf++)
                    mma16816(acc[mi][nf], af[mi], bf_[nf]);
        }
        __syncthreads();
    }

    const int gid = lid >> 2, tg = lid & 3;
#pragma unroll
    for (int mi = 0; mi < 2; mi++) {
        const int rA = m0 + mwarp * 32 + mi * 16 + gid;
        const int rB = rA + 8;
        float d2A = 0.f, d2B = 0.f;
        if (EPI == 1) { d2A = 1.0f / g_deg[rel][rA]; d2B = 1.0f / g_deg[rel][rB]; }
#pragma unroll
        for (int nf = 0; nf < NF; nf++) {
            const int c = n0 + nwarp * NW + nf * 8 + tg * 2;
            float2 vA = make_float2(acc[mi][nf][0], acc[mi][nf][1]);
            float2 vB = make_float2(acc[mi][nf][2], acc[mi][nf][3]);
            size_t offA = ((size_t)rel * BB + rA) * NTOT + c;
            size_t offB = ((size_t)rel * BB + rB) * NTOT + c;
            if (EPI == 0) {
                *(float2*)(g_XW + offA) = vA;
                *(float2*)(g_XW + offB) = vB;
            } else {
                *(float2*)(g_HW + offA) = vA;
                *(float2*)(g_HW + offB) = vB;
                float2 bb = *(const float2*)(b2 + c);
                *(float2*)(outall + offA) =
                    make_float2(d2A * vA.x + bb.x, d2A * vA.y + bb.y);
                *(float2*)(outall + offB) =
                    make_float2(d2B * vB.x + bb.x, d2B * vB.y + bb.y);
            }
        }
    }
}

__global__ void __launch_bounds__(256)
k_mma1() { hmma_body<INP, HID, 128, 0>(g_A1, g_B1, nullptr, nullptr); }

__global__ void __launch_bounds__(256)
k_mma2(float* __restrict__ outp, const float* __restrict__ b2) {
    hmma_body<HID, OUTC, 64, 1>(g_A2, g_B2, outp, b2);
}

// ---------------- edge scatter ----------------
__global__ void k_agg_edges_h() {
    const int r = blockIdx.y;
    int ne = g_kept[r];
    const float* S = g_XW + (size_t)r * BB * HID;
    float* D = g_AGG + (size_t)r * BB * HID;
    for (int e = blockIdx.x; e < ne; e += gridDim.x) {
        int s = g_ks[r][e], d = g_kd[r][e];
        float coeff = rsqrtf(g_deg[r][s] * g_deg[r][d]);
        const float* sp = S + (size_t)s * HID;
        float* dp = D + (size_t)d * HID;
        for (int c = threadIdx.x; c < HID; c += blockDim.x)
            atomicAdd(&dp[c], coeff * sp[c]);
    }
}
__global__ void k_agg_edges_o(float* __restrict__ outp) {
    const int r = blockIdx.y;
    int ne = g_kept[r];
    const float* S = g_HW + (size_t)r * BB * OUTC;
    float* D = outp + (size_t)r * BB * OUTC;
    for (int e = blockIdx.x; e < ne; e += gridDim.x) {
        int s = g_ks[r][e], d = g_kd[r][e];
        float coeff = rsqrtf(g_deg[r][s] * g_deg[r][d]);
        const float* sp = S + (size_t)s * OUTC;
        float* dp = D + (size_t)d * OUTC;
        for (int c = threadIdx.x; c < OUTC; c += blockDim.x)
            atomicAdd(&dp[c], coeff * sp[c]);
    }
}

// ---------------- BN stats: v = AGG + XW/deg, write back, accumulate ------
__global__ void k_bn_stats() {
    const int r = blockIdx.y;
    int c = threadIdx.x;  // 512
    int r0 = blockIdx.x * 32;
    float* agg = g_AGG + (size_t)r * BB * HID;
    const float* xw = g_XW + (size_t)r * BB * HID;
    float s = 0.0f, s2 = 0.0f;
#pragma unroll 4
    for (int i = 0; i < 32; i++) {
        float inv = 1.0f / g_deg[r][r0 + i];
        size_t off = (size_t)(r0 + i) * HID + c;
        float v = agg[off] + inv * xw[off];
        agg[off] = v;
        s += v;
        s2 += v * v;
    }
    atomicAdd(&g_sum[r][c], s);
    atomicAdd(&g_sumsq[r][c], s2);
}

// ---------------- BN normalize + 2-segment split conversion ---------------
__global__ void k_bn_norm_conv(const float* __restrict__ gamma,
                               const float* __restrict__ beta) {
    int idx = blockIdx.x * blockDim.x + threadIdx.x;  // RR*BB*HID
    int c = idx & (HID - 1);
    int i = (idx >> 9) & (BB - 1);
    int r = idx >> 20;
    const float invB = 1.0f / (float)BB;
    float mu = g_sum[r][c] * invB;
    float var = g_sumsq[r][c] * invB - mu * mu;
    float sc = rsqrtf(var + BN_EPS) * gamma[c];
    float sh = beta[c] - mu * sc;
    float h = g_AGG[idx] * sc + sh;
    __nv_bfloat16 hi, lo; split2(h, hi, lo);
    size_t base = ((size_t)r * BB + i) * K2_2;
    g_A2[base + c] = hi;
    g_A2[base + HID + c] = lo;
}

// ---------------- host launch ----------------
extern "C" void kernel_launch(void* const* d_in, const int* in_sizes, int n_in,
                              void* d_out, int out_size) {
    const float* feat = (const float*)d_in[0];
    const float* W1 = (const float*)d_in[1];
    // b1 cancels in BatchNorm
    const float* W2 = (const float*)d_in[3];
    const float* b2 = (const float*)d_in[4];
    const float* gamma = (const float*)d_in[5];
    const float* beta = (const float*)d_in[6];
    const int* ei = (const int*)d_in[7];
    const int* bn = (const int*)d_in[8];
    float* out = (float*)d_out;

    static cudaStream_t s_side = nullptr;
    static cudaEvent_t ev_fork = nullptr, ev_join = nullptr;
    if (!s_side) {
        cudaStreamCreateWithFlags(&s_side, cudaStreamNonBlocking);
        cudaEventCreateWithFlags(&ev_fork, cudaEventDisableTiming);
        cudaEventCreateWithFlags(&ev_join, cudaEventDisableTiming);
    }

    // single fused prologue (clears + pos + W conv + feature conv)
    k_pre<<<RR * BB * INP / 256, 256>>>(W1, W2, feat, bn);

    // fork: edge path on side stream
    cudaEventRecord(ev_fork, 0);
    cudaStreamWaitEvent(s_side, ev_fork, 0);
    { dim3 g((EE / 4 + 255) / 256, RR); k_scan<<<g, 256, 0, s_side>>>((const int4*)ei); }
    k_prefix_renum<<<RR, 1024, 0, s_side>>>();
    cudaEventRecord(ev_join, s_side);

    // compute path on main stream
    { dim3 g(HID / 128, BB / 128, RR); k_mma1<<<g, 256>>>(); }

    // join
    cudaStreamWaitEvent(0, ev_join, 0);

    { dim3 g(512, RR); k_agg_edges_h<<<g, 128>>>(); }
    { dim3 g(BB / 32, RR); k_bn_stats<<<g, 512>>>(); }
    k_bn_norm_conv<<<RR * BB * HID / 256, 256>>>(gamma, beta);
    { dim3 g(OUTC / 64, BB / 128, RR); k_mma2<<<g, 256>>>(out, b2); }
    { dim3 g(512, RR); k_agg_edges_o<<<g, 128>>>(out); }
}

// round 17
// speedup vs baseline: 1.4880x; 1.4880x over previous
#include <cuda_runtime.h>
#include <cuda_bf16.h>
#include <cstdint>

#define NN   50000
#define EE   1000000
#define BB   2048
#define RR   3
#define INP  256
#define HID  512
#define OUTC 256
#define BN_EPS 1e-5f
#define K3_1 (3*INP)    // 768
#define K3_2 (3*HID)    // 1536

// ---------------- device scratch ----------------
__device__ int   g_pos[NN];
__device__ int   g_appear[RR][BB];
__device__ float g_deg[RR][BB];
__device__ int   g_kept[RR];
__device__ int   g_ks[RR][EE];
__device__ int   g_kd[RR][EE];
__device__ __align__(16) __nv_bfloat16 g_A1[RR * BB * K3_1];
__device__ __align__(16) __nv_bfloat16 g_B1[HID * K3_1];
__device__ __align__(16) __nv_bfloat16 g_A2[RR * BB * K3_2];
__device__ __align__(16) __nv_bfloat16 g_B2[OUTC * K3_2];
__device__ __align__(16) float g_XW[RR * BB * HID];
__device__ __align__(16) float g_AGG[RR * BB * HID];
__device__ __align__(16) float g_HW[RR * BB * OUTC];
__device__ float g_sum[RR][HID];
__device__ float g_sumsq[RR][HID];

// ---------------- helpers ----------------
__device__ __forceinline__ uint32_t smem_u32(const void* p) {
    uint32_t a;
    asm("{ .reg .u64 t; cvta.to.shared.u64 t, %1; cvt.u32.u64 %0, t; }"
        : "=r"(a) : "l"(p));
    return a;
}
__device__ __forceinline__ void ldsm_x4(uint32_t& r0, uint32_t& r1,
                                        uint32_t& r2, uint32_t& r3, uint32_t a) {
    asm volatile("ldmatrix.sync.aligned.m8n8.x4.shared.b16 {%0,%1,%2,%3}, [%4];"
                 : "=r"(r0), "=r"(r1), "=r"(r2), "=r"(r3) : "r"(a));
}
__device__ __forceinline__ void mma16816(float* d, const uint32_t* a,
                                         const uint32_t* b) {
    asm volatile(
        "mma.sync.aligned.m16n8k16.row.col.f32.bf16.bf16.f32 "
        "{%0,%1,%2,%3}, {%4,%5,%6,%7}, {%8,%9}, {%0,%1,%2,%3};"
        : "+f"(d[0]), "+f"(d[1]), "+f"(d[2]), "+f"(d[3])
        : "r"(a[0]), "r"(a[1]), "r"(a[2]), "r"(a[3]), "r"(b[0]), "r"(b[1]));
}
__device__ __forceinline__ void split2(float x, __nv_bfloat16& hi, __nv_bfloat16& lo) {
    hi = __float2bfloat16(x);
    lo = __float2bfloat16(x - __bfloat162float(hi));
}
// split two floats -> packed hi pair and lo pair
__device__ __forceinline__ void split2x2(float a, float b, uint32_t& hip, uint32_t& lop) {
    __nv_bfloat16 ha = __float2bfloat16(a);
    __nv_bfloat16 hb = __float2bfloat16(b);
    __nv_bfloat16 la = __float2bfloat16(a - __bfloat162float(ha));
    __nv_bfloat16 lb = __float2bfloat16(b - __bfloat162float(hb));
    __nv_bfloat162 hp = __halves2bfloat162(ha, hb);
    __nv_bfloat162 lp = __halves2bfloat162(la, lb);
    hip = *(uint32_t*)&hp;
    lop = *(uint32_t*)&lp;
}

// ---------------- fused prologue (4-wide feature conversion) --------------
__global__ void k_pre(const float* __restrict__ W1, const float* __restrict__ W2,
                      const float* __restrict__ feat, const int* __restrict__ bn) {
    int idx = blockIdx.x * blockDim.x + threadIdx.x;   // grid: RR*BB*INP/4 threads
    if (idx < RR * BB * INP / 4) {
        int c4 = idx & (INP / 4 - 1);
        int i = (idx >> 6) & (BB - 1);
        int r = idx >> 17;                 // / (BB*INP/4)
        int c = c4 * 4;
        float4 f = *(const float4*)(feat + ((size_t)r * NN + bn[i]) * INP + c);
        uint32_t h0, l0, h1, l1;
        split2x2(f.x, f.y, h0, l0);
        split2x2(f.z, f.w, h1, l1);
        size_t base = ((size_t)r * BB + i) * K3_1;
        *(uint2*)(g_A1 + base + c) = make_uint2(h0, h1);
        *(uint2*)(g_A1 + base + INP + c) = make_uint2(l0, l1);
        *(uint2*)(g_A1 + base + 2 * INP + c) = make_uint2(h0, h1);
    }
    if (idx < NN) {
        int lo = 0, hi = BB - 1, res = -1;
        while (lo <= hi) {
            int mid = (lo + hi) >> 1;
            int v = bn[mid];
            if (v == idx) { res = mid; break; }
            if (v < idx) lo = mid + 1; else hi = mid - 1;
        }
        g_pos[idx] = res;
    }
    if (idx < RR * BB) ((int*)g_appear)[idx] = 0;
    if (idx < RR * HID) { ((float*)g_sum)[idx] = 0.f; ((float*)g_sumsq)[idx] = 0.f; }
    if (idx < RR) g_kept[idx] = 0;
    if (idx < HID * INP) {
        int n = idx >> 8, k = idx & (INP - 1);
        __nv_bfloat16 hi2, lo2; split2(W1[(size_t)k * HID + n], hi2, lo2);
        size_t base = (size_t)n * K3_1;
        g_B1[base + k] = hi2;
        g_B1[base + INP + k] = hi2;
        g_B1[base + 2 * INP + k] = lo2;
    }
    if (idx < OUTC * HID) {
        int n = idx >> 9, k = idx & (HID - 1);
        __nv_bfloat16 hi2, lo2; split2(W2[(size_t)k * OUTC + n], hi2, lo2);
        size_t base = (size_t)n * K3_2;
        g_B2[base + k] = hi2;
        g_B2[base + HID + k] = hi2;
        g_B2[base + 2 * HID + k] = lo2;
    }
}

// ---------------- AGG zeroing (separate, wide) ----------------
__global__ void k_zero_agg() {
    int idx = blockIdx.x * blockDim.x + threadIdx.x;
    if (idx < RR * BB * HID / 4)
        ((float4*)g_AGG)[idx] = make_float4(0.f, 0.f, 0.f, 0.f);
}

// ---------------- edge filtering (batched) ----------------
__global__ void k_scan(const int4* __restrict__ ei4) {
    const int r = blockIdx.y;
    const int4* src4 = ei4 + (size_t)r * 2 * (EE / 4);
    const int4* dst4 = src4 + EE / 4;
    int i = blockIdx.x * blockDim.x + threadIdx.x;
    if (i >= EE / 4) return;
    int4 s = src4[i], d = dst4[i];
    int ss[4] = {s.x, s.y, s.z, s.w};
    int dd[4] = {d.x, d.y, d.z, d.w};
#pragma unroll
    for (int j = 0; j < 4; j++) {
        int ps = g_pos[ss[j]];
        int pd = g_pos[dd[j]];
        if ((ps | pd) >= 0) {
            g_appear[r][ps] = 1;
            g_appear[r][pd] = 1;
            int ix = atomicAdd(&g_kept[r], 1);
            g_ks[r][ix] = ps;
            g_kd[r][ix] = pd;
        }
    }
}

// prefix scan + renumber + degree, one block per relation (1024 threads)
__global__ void __launch_bounds__(1024)
k_prefix_renum() {
    const int r = blockIdx.x;
    const int t = threadIdx.x;
    __shared__ int sc[1024];
    __shared__ int srank[BB];
    __shared__ float sdeg[BB];
    int a0 = g_appear[r][2 * t], a1 = g_appear[r][2 * t + 1];
    sc[t] = a0 + a1;
    sdeg[2 * t] = 0.f;
    sdeg[2 * t + 1] = 0.f;
    __syncthreads();
    for (int off = 1; off < 1024; off <<= 1) {
        int x = (t >= off) ? sc[t - off] : 0;
        __syncthreads();
        sc[t] += x;
        __syncthreads();
    }
    int pre = (t > 0) ? sc[t - 1] : 0;
    srank[2 * t] = pre + a0 - 1;
    srank[2 * t + 1] = pre + a0 + a1 - 1;
    __syncthreads();
    int ne = g_kept[r];
    for (int e = t; e < ne; e += 1024) {
        int rs = srank[g_ks[r][e]];
        int rd = srank[g_kd[r][e]];
        g_ks[r][e] = rs;
        g_kd[r][e] = rd;
        atomicAdd(&sdeg[rd], 1.0f);
    }
    __syncthreads();
    g_deg[r][2 * t] = 1.0f + sdeg[2 * t];
    g_deg[r][2 * t + 1] = 1.0f + sdeg[2 * t + 1];
}

// ---------------- HMMA GEMM (R12-exact) -----------------------------------
template <int K3, int NTOT, int NTILE, int EPI>
__device__ __forceinline__ void hmma_body(const __nv_bfloat16* __restrict__ Aall,
                                          const __nv_bfloat16* __restrict__ BT,
                                          float* __restrict__ outall,
                                          const float* __restrict__ b2) {
    constexpr int NW = NTILE / 2;
    constexpr int NF = NW / 8;
    __shared__ alignas(1024) __nv_bfloat16 sA[128 * 64];
    __shared__ alignas(1024) __nv_bfloat16 sB[NTILE * 64];

    const int tid = threadIdx.x, wid = tid >> 5, lid = tid & 31;
    const int mwarp = wid & 3, nwarp = wid >> 2;
    const int rel = blockIdx.z;
    const int m0 = blockIdx.y * 128, n0 = blockIdx.x * NTILE;
    const __nv_bfloat16* A = Aall + (size_t)rel * BB * K3;
    const uint32_t sA0 = smem_u32(sA), sB0 = smem_u32(sB);

    float acc[2][NF][4];
#pragma unroll
    for (int mi = 0; mi < 2; mi++)
#pragma unroll
        for (int nf = 0; nf < NF; nf++)
#pragma unroll
            for (int j = 0; j < 4; j++) acc[mi][nf][j] = 0.0f;

    const int a_row = lid & 15, a_kb = (lid >> 4) * 16;
    const int b_nn = ((lid >> 4) << 3) + (lid & 7), b_kb = ((lid >> 3) & 1) * 16;

    for (int kc = 0; kc < K3; kc += 64) {
#pragma unroll
        for (int it = 0; it < 4; it++) {
            int idx = it * 256 + tid;
            int r = idx >> 3, c16 = idx & 7;
            uint32_t byte = (uint32_t)(r * 128 + c16 * 16);
            uint32_t sw = byte ^ ((byte >> 3) & 0x70);
            *(uint4*)((char*)sA + sw) =
                *(const uint4*)(A + (size_t)(m0 + r) * K3 + kc + c16 * 8);
        }
#pragma unroll
        for (int it = 0; it < NTILE / 32; it++) {
            int idx = it * 256 + tid;
            int r = idx >> 3, c16 = idx & 7;
            uint32_t byte = (uint32_t)(r * 128 + c16 * 16);
            uint32_t sw = byte ^ ((byte >> 3) & 0x70);
            *(uint4*)((char*)sB + sw) =
                *(const uint4*)(BT + (size_t)(n0 + r) * K3 + kc + c16 * 8);
        }
        __syncthreads();
#pragma unroll
        for (int ks = 0; ks < 4; ks++) {
            const int kbyte = ks * 32;
            uint32_t af[2][4];
#pragma unroll
            for (int mi = 0; mi < 2; mi++) {
                int row = mwarp * 32 + mi * 16 + a_row;
                uint32_t byte = (uint32_t)(row * 128 + kbyte + a_kb);
                uint32_t sw = byte ^ ((byte >> 3) & 0x70);
                ldsm_x4(af[mi][0], af[mi][1], af[mi][2], af[mi][3], sA0 + sw);
            }
            uint32_t bf_[NF][2];
#pragma unroll
            for (int np = 0; np < NF / 2; np++) {
                int nn = nwarp * NW + np * 16 + b_nn;
                uint32_t byte = (uint32_t)(nn * 128 + kbyte + b_kb);
                uint32_t sw = byte ^ ((byte >> 3) & 0x70);
                uint32_t r0, r1, r2, r3;
                ldsm_x4(r0, r1, r2, r3, sB0 + sw);
                bf_[2 * np][0] = r0; bf_[2 * np][1] = r1;
                bf_[2 * np + 1][0] = r2; bf_[2 * np + 1][1] = r3;
            }
#pragma unroll
            for (int mi = 0; mi < 2; mi++)
#pragma unroll
                for (int nf = 0; nf < NF; nf++)
                    mma16816(acc[mi][nf], af[mi], bf_[nf]);
        }
        __syncthreads();
    }

    const int gid = lid >> 2, tg = lid & 3;
#pragma unroll
    for (int mi = 0; mi < 2; mi++) {
        const int rA = m0 + mwarp * 32 + mi * 16 + gid;
        const int rB = rA + 8;
        float d2A = 0.f, d2B = 0.f;
        if (EPI == 1) { d2A = 1.0f / g_deg[rel][rA]; d2B = 1.0f / g_deg[rel][rB]; }
#pragma unroll
        for (int nf = 0; nf < NF; nf++) {
            const int c = n0 + nwarp * NW + nf * 8 + tg * 2;
            float2 vA = make_float2(acc[mi][nf][0], acc[mi][nf][1]);
            float2 vB = make_float2(acc[mi][nf][2], acc[mi][nf][3]);
            size_t offA = ((size_t)rel * BB + rA) * NTOT + c;
            size_t offB = ((size_t)rel * BB + rB) * NTOT + c;
            if (EPI == 0) {
                *(float2*)(g_XW + offA) = vA;
                *(float2*)(g_XW + offB) = vB;
            } else {
                *(float2*)(g_HW + offA) = vA;
                *(float2*)(g_HW + offB) = vB;
                float2 bb = *(const float2*)(b2 + c);
                *(float2*)(outall + offA) =
                    make_float2(d2A * vA.x + bb.x, d2A * vA.y + bb.y);
                *(float2*)(outall + offB) =
                    make_float2(d2B * vB.x + bb.x, d2B * vB.y + bb.y);
            }
        }
    }
}

__global__ void __launch_bounds__(256)
k_mma1() { hmma_body<K3_1, HID, 128, 0>(g_A1, g_B1, nullptr, nullptr); }

__global__ void __launch_bounds__(256)
k_mma2(float* __restrict__ outp, const float* __restrict__ b2) {
    hmma_body<K3_2, OUTC, 64, 1>(g_A2, g_B2, outp, b2);
}

// ---------------- edge scatter ----------------
__global__ void k_agg_edges_h() {
    const int r = blockIdx.y;
    int ne = g_kept[r];
    const float* S = g_XW + (size_t)r * BB * HID;
    float* D = g_AGG + (size_t)r * BB * HID;
    for (int e = blockIdx.x; e < ne; e += gridDim.x) {
        int s = g_ks[r][e], d = g_kd[r][e];
        float coeff = rsqrtf(g_deg[r][s] * g_deg[r][d]);
        const float* sp = S + (size_t)s * HID;
        float* dp = D + (size_t)d * HID;
        for (int c = threadIdx.x; c < HID; c += blockDim.x)
            atomicAdd(&dp[c], coeff * sp[c]);
    }
}
__global__ void k_agg_edges_o(float* __restrict__ outp) {
    const int r = blockIdx.y;
    int ne = g_kept[r];
    const float* S = g_HW + (size_t)r * BB * OUTC;
    float* D = outp + (size_t)r * BB * OUTC;
    for (int e = blockIdx.x; e < ne; e += gridDim.x) {
        int s = g_ks[r][e], d = g_kd[r][e];
        float coeff = rsqrtf(g_deg[r][s] * g_deg[r][d]);
        const float* sp = S + (size_t)s * OUTC;
        float* dp = D + (size_t)d * OUTC;
        for (int c = threadIdx.x; c < OUTC; c += blockDim.x)
            atomicAdd(&dp[c], coeff * sp[c]);
    }
}

// ---------------- BN stats: v = AGG + XW/deg, write back, accumulate ------
__global__ void k_bn_stats() {
    const int r = blockIdx.y;
    int c = threadIdx.x;  // 512
    int r0 = blockIdx.x * 32;
    float* agg = g_AGG + (size_t)r * BB * HID;
    const float* xw = g_XW + (size_t)r * BB * HID;
    float s = 0.0f, s2 = 0.0f;
#pragma unroll 4
    for (int i = 0; i < 32; i++) {
        float inv = 1.0f / g_deg[r][r0 + i];
        size_t off = (size_t)(r0 + i) * HID + c;
        float v = agg[off] + inv * xw[off];
        agg[off] = v;
        s += v;
        s2 += v * v;
    }
    atomicAdd(&g_sum[r][c], s);
    atomicAdd(&g_sumsq[r][c], s2);
}

// ---------------- BN normalize + split conversion (4-wide) ----------------
__global__ void k_bn_norm_conv(const float* __restrict__ gamma,
                               const float* __restrict__ beta) {
    int idx = blockIdx.x * blockDim.x + threadIdx.x;  // RR*BB*HID/4
    int c4 = idx & (HID / 4 - 1);
    int i = (idx >> 7) & (BB - 1);
    int r = idx >> 18;                 // / (BB*HID/4)
    int c = c4 * 4;
    const float invB = 1.0f / (float)BB;
    float4 vsum = *(const float4*)(&g_sum[r][c]);
    float4 vsq = *(const float4*)(&g_sumsq[r][c]);
    float4 vg = *(const float4*)(gamma + c);
    float4 vb = *(const float4*)(beta + c);
    float4 va = *(const float4*)(g_AGG + ((size_t)r * BB + i) * HID + c);
    float h[4];
#pragma unroll
    for (int j = 0; j < 4; j++) {
        float mu = (&vsum.x)[j] * invB;
        float var = (&vsq.x)[j] * invB - mu * mu;
        float sc = rsqrtf(var + BN_EPS) * (&vg.x)[j];
        float sh = (&vb.x)[j] - mu * sc;
        h[j] = (&va.x)[j] * sc + sh;
    }
    uint32_t h0, l0, h1, l1;
    split2x2(h[0], h[1], h0, l0);
    split2x2(h[2], h[3], h1, l1);
    size_t base = ((size_t)r * BB + i) * K3_2;
    *(uint2*)(g_A2 + base + c) = make_uint2(h0, h1);
    *(uint2*)(g_A2 + base + HID + c) = make_uint2(l0, l1);
    *(uint2*)(g_A2 + base + 2 * HID + c) = make_uint2(h0, h1);
}

// ---------------- host launch ----------------
extern "C" void kernel_launch(void* const* d_in, const int* in_sizes, int n_in,
                              void* d_out, int out_size) {
    const float* feat = (const float*)d_in[0];
    const float* W1 = (const float*)d_in[1];
    // b1 cancels in BatchNorm
    const float* W2 = (const float*)d_in[3];
    const float* b2 = (const float*)d_in[4];
    const float* gamma = (const float*)d_in[5];
    const float* beta = (const float*)d_in[6];
    const int* ei = (const int*)d_in[7];
    const int* bn = (const int*)d_in[8];
    float* out = (float*)d_out;

    static cudaStream_t s_side = nullptr;
    static cudaEvent_t ev_fork = nullptr, ev_join = nullptr;
    if (!s_side) {
        cudaStreamCreateWithFlags(&s_side, cudaStreamNonBlocking);
        cudaEventCreateWithFlags(&ev_fork, cudaEventDisableTiming);
        cudaEventCreateWithFlags(&ev_join, cudaEventDisableTiming);
    }

    // prologue: feature/W conversion + pos + clears; AGG zero on side stream
    k_pre<<<RR * BB * INP / 4 / 256, 256>>>(W1, W2, feat, bn);

    cudaEventRecord(ev_fork, 0);
    cudaStreamWaitEvent(s_side, ev_fork, 0);
    k_zero_agg<<<RR * BB * HID / 4 / 256, 256, 0, s_side>>>();
    { dim3 g((EE / 4 + 255) / 256, RR); k_scan<<<g, 256, 0, s_side>>>((const int4*)ei); }
    k_prefix_renum<<<RR, 1024, 0, s_side>>>();
    cudaEventRecord(ev_join, s_side);

    // compute path on main stream
    { dim3 g(HID / 128, BB / 128, RR); k_mma1<<<g, 256>>>(); }

    // join
    cudaStreamWaitEvent(0, ev_join, 0);

    { dim3 g(512, RR); k_agg_edges_h<<<g, 128>>>(); }
    { dim3 g(BB / 32, RR); k_bn_stats<<<g, 512>>>(); }
    k_bn_norm_conv<<<RR * BB * HID / 4 / 256, 256>>>(gamma, beta);
    { dim3 g(OUTC / 64, BB / 128, RR); k_mma2<<<g, 256>>>(out, b2); }
    { dim3 g(512, RR); k_agg_edges_o<<<g, 128>>>(out); }
}